// round 15
// baseline (speedup 1.0000x reference)
#include <cuda_runtime.h>
#include <cuda_bf16.h>
#include <cstdint>
#include <math.h>

#define BATCH 2
#define CH    256
#define NPIX  4096
#define NGRP  32
#define CPG   (CH/NGRP)
#define GN_EPS 1e-6f
#define QSCALE 0.0625f
#define KSPLIT 2048      // PV split-K half

// ---------------- scratch (static device globals; no allocation) ----------------
__device__ __align__(256) __nv_bfloat16 g_sb[(size_t)BATCH*NPIX*NPIX]; // exp-scores bf16
__device__ __align__(256) __nv_bfloat16 g_hb[BATCH*CH*NPIX];
__device__ __align__(256) __nv_bfloat16 g_qb[BATCH*CH*NPIX];
__device__ __align__(256) __nv_bfloat16 g_kb[BATCH*CH*NPIX];
__device__ __align__(256) __nv_bfloat16 g_vb[BATCH*CH*NPIX];
__device__ __align__(256) float         g_pv[(size_t)BATCH*2*CH*NPIX]; // PV fp32 partials
__device__ __align__(256) float         g_psum[(size_t)BATCH*NPIX*32]; // row partial sums
__device__ __align__(256) float         g_rinv[BATCH*NPIX];            // 1/rowsum
__device__ __align__(256) float         g_gnp[BATCH*NGRP*8*2];         // GN partial stats
__device__ __align__(256) __nv_bfloat16 g_wb[3*CH*CH];   // stacked wq,wk,wv bf16
__device__ __align__(256) __nv_bfloat16 g_wpb[CH*CH];
__device__ __align__(256) float         g_bias[3*CH];    // stacked bq,bk,bv

// ---------------- PTX helpers ----------------
__device__ __forceinline__ uint32_t cvta_smem(const void* p) {
    uint32_t a;
    asm("{ .reg .u64 t; cvta.to.shared.u64 t, %1; cvt.u32.u64 %0, t; }" : "=r"(a) : "l"(p));
    return a;
}
__device__ __forceinline__ void cp16(uint32_t s, const void* g) {
    asm volatile("cp.async.cg.shared.global [%0], [%1], 16;" :: "r"(s), "l"(g) : "memory");
}
__device__ __forceinline__ void cp_commit() { asm volatile("cp.async.commit_group;" ::: "memory"); }
template<int N> __device__ __forceinline__ void cp_wait() {
    asm volatile("cp.async.wait_group %0;" :: "n"(N) : "memory");
}
__device__ __forceinline__ void sts128(uint32_t a, uint4 v) {
    asm volatile("st.shared.v4.b32 [%0], {%1,%2,%3,%4};"
                 :: "r"(a), "r"(v.x), "r"(v.y), "r"(v.z), "r"(v.w) : "memory");
}
__device__ __forceinline__ void ldsm4(uint32_t& r0, uint32_t& r1, uint32_t& r2, uint32_t& r3, uint32_t a) {
    asm volatile("ldmatrix.sync.aligned.m8n8.x4.shared.b16 {%0,%1,%2,%3}, [%4];"
                 : "=r"(r0), "=r"(r1), "=r"(r2), "=r"(r3) : "r"(a));
}
__device__ __forceinline__ void ldsm4t(uint32_t& r0, uint32_t& r1, uint32_t& r2, uint32_t& r3, uint32_t a) {
    asm volatile("ldmatrix.sync.aligned.m8n8.x4.trans.shared.b16 {%0,%1,%2,%3}, [%4];"
                 : "=r"(r0), "=r"(r1), "=r"(r2), "=r"(r3) : "r"(a));
}
#define MMA_OP(d, a0,a1,a2,a3, b0,b1) \
    asm volatile("mma.sync.aligned.m16n8k16.row.col.f32.bf16.bf16.f32 " \
                 "{%0,%1,%2,%3}, {%4,%5,%6,%7}, {%8,%9}, {%0,%1,%2,%3};" \
                 : "+f"((d)[0]), "+f"((d)[1]), "+f"((d)[2]), "+f"((d)[3]) \
                 : "r"(a0), "r"(a1), "r"(a2), "r"(a3), "r"(b0), "r"(b1))

__device__ __forceinline__ __nv_bfloat162 pack_bf2(float v0, float v1) {
    __nv_bfloat162 r;
    r.x = __float2bfloat16(v0);
    r.y = __float2bfloat16(v1);
    return r;
}

// ================= bf16 mma.sync GEMM (fp32 accum), BK=64, warp-tile templated =========
// WN_: warp-grid n-count. WM_=2 fixed. THREADS = 64*WN_. Warp tile = 64 x (128/WN_).
// ALAY: 0 = A[m*lda+k], 1 = A[k*lda+m] (trans)
// BLAY: 0 = B[n*ldb+k], 1 = B[k*ldb+n] (trans), 2 = computed bf16((pv0+pv1)*rinv) (trans)
// EPI : 0 fp32 +bias+resid; 1 bf16; 2 fused qkv; 3 split-K fp32 partial; 4 exp+rowsums
template<int ALAY, int BLAY, int EPI, int STAGES, int WN_>
__global__ __launch_bounds__(64*WN_, 2)
void mma_gemm(const __nv_bfloat16* __restrict__ A, const __nv_bfloat16* __restrict__ B,
              const float* __restrict__ bias, float* __restrict__ OutF,
              __nv_bfloat16* __restrict__ O0, __nv_bfloat16* __restrict__ O1,
              __nv_bfloat16* __restrict__ O2,
              const float* __restrict__ R, float scale,
              int K, int lda, int ldb, int ldo,
              size_t sA, size_t sB, size_t sO)
{
    constexpr int THREADS = 64 * WN_;
    constexpr int NSPAN = 128 / WN_;        // n-span per warp
    constexpr int NI = NSPAN / 8;           // n8 fragments per warp
    constexpr int NP = NSPAN / 16;          // merged x4 B loads per kk
    constexpr int LOOP = 1024 / THREADS;    // 16B chunks per thread per operand
    constexpr uint32_t ASZ = (ALAY == 0) ? 128u*144u : 64u*272u;
    constexpr uint32_t BSZ = (BLAY == 0) ? 128u*144u : 64u*272u;

    extern __shared__ char smem[];
    const uint32_t sbase = cvta_smem(smem);

    const int bz = blockIdx.z;
    const int b  = (EPI == 3) ? (bz >> 1) : bz;
    A += (size_t)b * sA;
    if (BLAY != 2) B += (size_t)b * sB;
    if (EPI == 0) { OutF += (size_t)b * sO; R += (size_t)b * sO; }
    else if (EPI == 1 || EPI == 4) O0 += (size_t)b * sO;
    else if (EPI == 2) { O0 += (size_t)b * sO; O1 += (size_t)b * sO; O2 += (size_t)b * sO; }
    else {
        const int sp = bz & 1;
        A += (size_t)sp * KSPLIT;
        B += (size_t)sp * KSPLIT;
        OutF += (size_t)bz * sO;
    }

    const int tid  = threadIdx.x;
    const int lane = tid & 31;
    const int wid  = tid >> 5;
    const int wm   = wid / WN_;
    const int wn   = wid % WN_;
    const int m0   = blockIdx.y * 128;
    const int n0   = blockIdx.x * 128;

    float acc[4][NI][4];
    #pragma unroll
    for (int a = 0; a < 4; a++)
        #pragma unroll
        for (int bb2 = 0; bb2 < NI; bb2++)
            #pragma unroll
            for (int c = 0; c < 4; c++) acc[a][bb2][c] = 0.f;

    const int S = K / 64;

    auto load_stage = [&](int s, int slot) {
        const int k0 = s * 64;
        const uint32_t ab = sbase + (uint32_t)slot * (ASZ + BSZ);
        const uint32_t bb = ab + ASZ;
        #pragma unroll
        for (int r = 0; r < LOOP; r++) {
            const int id = tid + THREADS * r;
            if (ALAY == 0) {
                int row = id >> 3, c = id & 7;
                cp16(ab + (uint32_t)row*144u + (uint32_t)c*16u,
                     A + (size_t)(m0 + row)*lda + k0 + c*8);
            } else {
                int row = id >> 4, c = id & 15;
                cp16(ab + (uint32_t)row*272u + (uint32_t)c*16u,
                     A + (size_t)(k0 + row)*lda + m0 + c*8);
            }
            if (BLAY == 0) {
                int row = id >> 3, c = id & 7;
                cp16(bb + (uint32_t)row*144u + (uint32_t)c*16u,
                     B + (size_t)(n0 + row)*ldb + k0 + c*8);
            } else if (BLAY == 1) {
                int row = id >> 4, c = id & 15;
                cp16(bb + (uint32_t)row*272u + (uint32_t)c*16u,
                     B + (size_t)(k0 + row)*ldb + n0 + c*8);
            } else { // BLAY == 2: compute bf16((pv0+pv1)*rinv) -> trans smem
                int row = id >> 4, c = id & 15;
                const size_t sCN_ = (size_t)CH * NPIX;
                const float* p0 = &g_pv[((size_t)b*2 + 0)*sCN_ + (size_t)(k0 + row)*NPIX + n0 + c*8];
                const float* p1 = p0 + sCN_;
                float4 x0 = *(const float4*)p0, x1 = *(const float4*)(p0 + 4);
                float4 y0 = *(const float4*)p1, y1 = *(const float4*)(p1 + 4);
                const float* rp = &g_rinv[b*NPIX + n0 + c*8];
                float4 r0 = *(const float4*)rp, r1 = *(const float4*)(rp + 4);
                __nv_bfloat162 h0 = pack_bf2((x0.x + y0.x)*r0.x, (x0.y + y0.y)*r0.y);
                __nv_bfloat162 h1 = pack_bf2((x0.z + y0.z)*r0.z, (x0.w + y0.w)*r0.w);
                __nv_bfloat162 h2 = pack_bf2((x1.x + y1.x)*r1.x, (x1.y + y1.y)*r1.y);
                __nv_bfloat162 h3 = pack_bf2((x1.z + y1.z)*r1.z, (x1.w + y1.w)*r1.w);
                uint4 u;
                u.x = *(const uint32_t*)&h0; u.y = *(const uint32_t*)&h1;
                u.z = *(const uint32_t*)&h2; u.w = *(const uint32_t*)&h3;
                sts128(bb + (uint32_t)row*272u + (uint32_t)c*16u, u);
            }
        }
        cp_commit();
    };

    const int g4   = lane >> 3;
    const int lr8  = lane & 7;
    const int at_k = lr8 + (g4 & 1) * 8;
    const int at_m = (g4 >> 1) * 8;
    const int ap_r = lane & 15;
    const int ap_c = lane >> 4;
    const int b_kh = (lane >> 3) & 1;
    const int b_nh = (lane >> 4);

    const int pre = (S < STAGES - 1) ? S : (STAGES - 1);
    for (int p = 0; p < pre; p++) load_stage(p, p);

    for (int s = 0; s < S; s++) {
        cp_wait<STAGES - 2>();
        __syncthreads();
        if (s + STAGES - 1 < S) load_stage(s + STAGES - 1, (s + STAGES - 1) % STAGES);

        const uint32_t ab = sbase + (uint32_t)(s % STAGES) * (ASZ + BSZ);
        const uint32_t bb = ab + ASZ;

        #pragma unroll
        for (int kk = 0; kk < 4; kk++) {      // 4 x k16 = BK 64
            uint32_t A0[4], A1[4], A2[4], A3[4];
            #pragma unroll
            for (int mi = 0; mi < 4; mi++) {
                uint32_t r0, r1, r2, r3, addr;
                if (ALAY == 0) {
                    addr = ab + (uint32_t)(wm*64 + mi*16 + ap_r)*144u
                              + (uint32_t)(kk*32 + ap_c*16);
                    ldsm4(r0, r1, r2, r3, addr);
                    A0[mi] = r0; A1[mi] = r1; A2[mi] = r2; A3[mi] = r3;
                } else {
                    addr = ab + (uint32_t)(kk*16 + at_k)*272u
                              + (uint32_t)(wm*64 + mi*16 + at_m)*2u;
                    ldsm4t(r0, r1, r2, r3, addr);
                    A0[mi] = r0; A1[mi] = r2; A2[mi] = r1; A3[mi] = r3;
                }
            }
            uint32_t B0[NI], B1[NI];
            #pragma unroll
            for (int np = 0; np < NP; np++) {
                uint32_t r0, r1, r2, r3, addr;
                if (BLAY == 0) {
                    int nrow = wn*NSPAN + np*16 + b_nh*8 + lr8;
                    int col  = kk*32 + b_kh*16;
                    addr = bb + (uint32_t)nrow*144u + (uint32_t)col;
                    ldsm4(r0, r1, r2, r3, addr);
                } else {
                    int krow = kk*16 + b_kh*8 + lr8;
                    int ncol = wn*NSPAN + np*16 + b_nh*8;
                    addr = bb + (uint32_t)krow*272u + (uint32_t)ncol*2u;
                    ldsm4t(r0, r1, r2, r3, addr);
                }
                B0[2*np]   = r0; B1[2*np]   = r1;
                B0[2*np+1] = r2; B1[2*np+1] = r3;
            }
            #pragma unroll
            for (int mi = 0; mi < 4; mi++)
                #pragma unroll
                for (int ni = 0; ni < NI; ni++)
                    MMA_OP(acc[mi][ni], A0[mi], A1[mi], A2[mi], A3[mi], B0[ni], B1[ni]);
        }
    }

    // ---------------- epilogue ----------------
    const int em = (lane >> 2);
    const int en = (lane & 3) * 2;
    const int seg = m0 >> 8;
    __nv_bfloat16* Oseg = (EPI == 2) ? (seg == 0 ? O0 : (seg == 1 ? O1 : O2)) : O0;
    const float segscale = (EPI == 2) ? (seg == 0 ? QSCALE : 1.0f) : scale;

    float* rowpart = (float*)smem;           // EPI==4: reuse pipeline smem (WN_*128 floats)
    if (EPI == 4) __syncthreads();

    #pragma unroll
    for (int mi = 0; mi < 4; mi++) {
        const int mA = m0 + wm*64 + mi*16 + em;
        const int mB = mA + 8;
        float sA_ = 0.f, sB_ = 0.f;
        #pragma unroll
        for (int ni = 0; ni < NI; ni++) {
            const int n = n0 + wn*NSPAN + ni*8 + en;
            float* d = acc[mi][ni];
            if (EPI == 0) {
                const float bvA = bias[mA], bvB = bias[mB];
                float2 oA = { (d[0] + bvA)*scale, (d[1] + bvA)*scale };
                float2 oB = { (d[2] + bvB)*scale, (d[3] + bvB)*scale };
                float2 rA = *(const float2*)&R[(size_t)mA*ldo + n];
                float2 rB = *(const float2*)&R[(size_t)mB*ldo + n];
                oA.x += rA.x; oA.y += rA.y; oB.x += rB.x; oB.y += rB.y;
                *(float2*)&OutF[(size_t)mA*ldo + n] = oA;
                *(float2*)&OutF[(size_t)mB*ldo + n] = oB;
            } else if (EPI == 1) {
                *(__nv_bfloat162*)&O0[(size_t)mA*ldo + n] = pack_bf2(d[0]*scale, d[1]*scale);
                *(__nv_bfloat162*)&O0[(size_t)mB*ldo + n] = pack_bf2(d[2]*scale, d[3]*scale);
            } else if (EPI == 2) {
                const float bvA = bias[mA], bvB = bias[mB];
                const int rA = mA & 255, rB = mB & 255;
                *(__nv_bfloat162*)&Oseg[(size_t)rA*ldo + n] =
                    pack_bf2((d[0] + bvA)*segscale, (d[1] + bvA)*segscale);
                *(__nv_bfloat162*)&Oseg[(size_t)rB*ldo + n] =
                    pack_bf2((d[2] + bvB)*segscale, (d[3] + bvB)*segscale);
            } else if (EPI == 3) {
                float2 oA = { d[0], d[1] };
                float2 oB = { d[2], d[3] };
                *(float2*)&OutF[(size_t)mA*ldo + n] = oA;
                *(float2*)&OutF[(size_t)mB*ldo + n] = oB;
            } else { // EPI == 4: exp + partial row sums
                float e0 = __expf(d[0]), e1 = __expf(d[1]);
                float e2 = __expf(d[2]), e3 = __expf(d[3]);
                *(__nv_bfloat162*)&O0[(size_t)mA*ldo + n] = pack_bf2(e0, e1);
                *(__nv_bfloat162*)&O0[(size_t)mB*ldo + n] = pack_bf2(e2, e3);
                sA_ += e0 + e1;
                sB_ += e2 + e3;
            }
        }
        if (EPI == 4) {
            sA_ += __shfl_xor_sync(0xFFFFFFFFu, sA_, 1);
            sA_ += __shfl_xor_sync(0xFFFFFFFFu, sA_, 2);
            sB_ += __shfl_xor_sync(0xFFFFFFFFu, sB_, 1);
            sB_ += __shfl_xor_sync(0xFFFFFFFFu, sB_, 2);
            if ((lane & 3) == 0) {
                rowpart[wn*128 + (wm*64 + mi*16 + em)]     = sA_;
                rowpart[wn*128 + (wm*64 + mi*16 + em + 8)] = sB_;
            }
        }
    }
    if (EPI == 4) {
        __syncthreads();
        if (tid < 128) {
            float s = 0.f;
            #pragma unroll
            for (int w = 0; w < WN_; w++) s += rowpart[w*128 + tid];
            g_psum[((size_t)b*NPIX + m0 + tid)*32 + blockIdx.x] = s;
        }
    }
}

// ---------------- row sums -> 1/sum ----------------
__global__ void rowsum_kernel() {
    const int r = blockIdx.x * 256 + threadIdx.x;
    const float4* p = (const float4*)&g_psum[(size_t)r * 32];
    float s = 0.f;
    #pragma unroll
    for (int i = 0; i < 8; i++) {
        float4 v = p[i];
        s += v.x + v.y + v.z + v.w;
    }
    g_rinv[r] = 1.0f / s;
}

// ---------------- prep: stack + convert weights/biases ----------------
__global__ void prep_kernel(const float* __restrict__ wq, const float* __restrict__ wk,
                            const float* __restrict__ wv, const float* __restrict__ wp,
                            const float* __restrict__ bq, const float* __restrict__ bk,
                            const float* __restrict__ bv) {
    int i = blockIdx.x * 256 + threadIdx.x;
    if (i < 3*CH*CH) {
        int r = i / CH;
        int seg = r >> 8;
        const float* w = seg == 0 ? wq : (seg == 1 ? wk : wv);
        g_wb[i] = __float2bfloat16(w[(size_t)(r & 255)*CH + (i % CH)]);
    } else if (i < 4*CH*CH) {
        int j = i - 3*CH*CH;
        g_wpb[j] = __float2bfloat16(wp[j]);
    } else if (i < 4*CH*CH + 3*CH) {
        int j = i - 4*CH*CH;
        int seg = j >> 8;
        const float* bb = seg == 0 ? bq : (seg == 1 ? bk : bv);
        g_bias[j] = bb[j & 255];
    }
}

// ---------------- GroupNorm phase 1: per-channel partial sums ----------------
__global__ void gn_stats(const float* __restrict__ x) {
    const int id = blockIdx.x;
    const size_t base = (size_t)id * NPIX;
    const float4* xp4 = (const float4*)(x + base);
    const int tid = threadIdx.x;
    float s = 0.f, s2 = 0.f;
    #pragma unroll
    for (int i = 0; i < 4; i++) {
        float4 v = xp4[tid + 256*i];
        s  += v.x + v.y + v.z + v.w;
        s2 += v.x*v.x + v.y*v.y + v.z*v.z + v.w*v.w;
    }
    __shared__ float sh[256], sh2[256];
    sh[tid] = s; sh2[tid] = s2;
    __syncthreads();
    for (int o = 128; o > 0; o >>= 1) {
        if (tid < o) { sh[tid] += sh[tid+o]; sh2[tid] += sh2[tid+o]; }
        __syncthreads();
    }
    if (tid == 0) {
        g_gnp[id*2]     = sh[0];
        g_gnp[id*2 + 1] = sh2[0];
    }
}

// ---------------- GroupNorm phase 2: finalize + apply -> bf16 h ----------------
__global__ void gn_apply(const float* __restrict__ x,
                         const float* __restrict__ gamma,
                         const float* __restrict__ beta) {
    const int id = blockIdx.x;
    const int bg = id >> 3;
    const int g  = bg % NGRP;
    const int sl = id & 7;
    float s = 0.f, s2 = 0.f;
    #pragma unroll
    for (int k = 0; k < 8; k++) {
        s  += g_gnp[(bg*8 + k)*2];
        s2 += g_gnp[(bg*8 + k)*2 + 1];
    }
    const float inv_n = 1.0f / (float)(CPG*NPIX);
    const float mean  = s * inv_n;
    const float var   = s2 * inv_n - mean*mean;
    const float rstd  = rsqrtf(var + GN_EPS);
    const int ch = g*CPG + sl;
    const float ga = gamma[ch] * rstd;
    const float be = beta[ch] - mean * ga;

    const size_t base = (size_t)id * NPIX;
    const float4* xp4 = (const float4*)(x + base);
    __nv_bfloat162* hb2 = (__nv_bfloat162*)(g_hb + base);
    const int tid = threadIdx.x;
    #pragma unroll
    for (int i = 0; i < 4; i++) {
        float4 v = xp4[tid + 256*i];
        hb2[(tid + 256*i)*2]     = pack_bf2(v.x*ga + be, v.y*ga + be);
        hb2[(tid + 256*i)*2 + 1] = pack_bf2(v.z*ga + be, v.w*ga + be);
    }
}

// ---------------- launch ----------------
extern "C" void kernel_launch(void* const* d_in, const int* in_sizes, int n_in,
                              void* d_out, int out_size) {
    const float* x     = (const float*)d_in[0];
    const float* gamma = (const float*)d_in[1];
    const float* beta  = (const float*)d_in[2];
    const float* wq = (const float*)d_in[3];
    const float* bq = (const float*)d_in[4];
    const float* wk = (const float*)d_in[5];
    const float* bk = (const float*)d_in[6];
    const float* wv = (const float*)d_in[7];
    const float* bv = (const float*)d_in[8];
    const float* wp = (const float*)d_in[9];
    const float* bp = (const float*)d_in[10];
    float* out = (float*)d_out;

    __nv_bfloat16 *p_sb, *p_hb, *p_qb, *p_kb, *p_vb, *p_wb, *p_wpb;
    float *p_bias, *p_pv;
    cudaGetSymbolAddress((void**)&p_sb,  g_sb);
    cudaGetSymbolAddress((void**)&p_hb,  g_hb);
    cudaGetSymbolAddress((void**)&p_qb,  g_qb);
    cudaGetSymbolAddress((void**)&p_kb,  g_kb);
    cudaGetSymbolAddress((void**)&p_vb,  g_vb);
    cudaGetSymbolAddress((void**)&p_wb,  g_wb);
    cudaGetSymbolAddress((void**)&p_wpb, g_wpb);
    cudaGetSymbolAddress((void**)&p_bias, g_bias);
    cudaGetSymbolAddress((void**)&p_pv,  g_pv);

    // smem per stage (BK=64): plain = 128*144 = 18432, trans = 64*272 = 17408
    const int SM_QKV = 2 * (18432 + 17408);   // A plain, B trans = 71680
    const int SM_SCO = 2 * (17408 + 17408);   // both trans       = 69632
    const int SM_PV  = 2 * (18432 + 18432);   // both plain       = 73728
    const int SM_PRJ = 2 * (18432 + 17408);   // A plain, B computed-trans = 71680
    cudaFuncSetAttribute(mma_gemm<0,1,2,2,4>, cudaFuncAttributeMaxDynamicSharedMemorySize, SM_QKV);
    cudaFuncSetAttribute(mma_gemm<1,1,4,2,2>, cudaFuncAttributeMaxDynamicSharedMemorySize, SM_SCO);
    cudaFuncSetAttribute(mma_gemm<0,0,3,2,4>, cudaFuncAttributeMaxDynamicSharedMemorySize, SM_PV);
    cudaFuncSetAttribute(mma_gemm<0,2,0,2,4>, cudaFuncAttributeMaxDynamicSharedMemorySize, SM_PRJ);

    const size_t sCN = (size_t)CH * NPIX;
    const size_t sNN = (size_t)NPIX * NPIX;

    // 0. prep weights/biases
    prep_kernel<<<(4*CH*CH + 3*CH + 255)/256, 256>>>(wq, wk, wv, wp, bq, bk, bv);

    // 1. GroupNorm (two-phase) -> bf16 h
    gn_stats<<<BATCH*NGRP*8, 256>>>(x);
    gn_apply<<<BATCH*NGRP*8, 256>>>(x, gamma, beta);

    // 2. fused qkv: 8-warp config
    dim3 gqkv(NPIX/128, (3*CH)/128, BATCH);
    mma_gemm<0,1,2,2,4><<<gqkv, 256, SM_QKV>>>(
        p_wb, p_hb, p_bias, nullptr, p_qb, p_kb, p_vb,
        nullptr, 1.0f, CH, CH, NPIX, NPIX, 0, sCN, sCN);

    // 3. exp-scores: 4-warp config (warp tile 64x64 halves smem traffic/MAC)
    dim3 gsc(NPIX/128, NPIX/128, BATCH);
    mma_gemm<1,1,4,2,2><<<gsc, 128, SM_SCO>>>(
        p_qb, p_kb, nullptr, nullptr, p_sb, nullptr, nullptr,
        nullptr, 1.0f, CH, NPIX, NPIX, NPIX, sCN, sCN, sNN);

    // 4. row sums -> 1/sum
    rowsum_kernel<<<BATCH*NPIX/256, 256>>>();

    // 5. PV split-K=2: 8-warp config
    dim3 gpv(NPIX/128, CH/128, BATCH*2);
    mma_gemm<0,0,3,2,4><<<gpv, 256, SM_PV>>>(
        p_vb, p_sb, nullptr, p_pv, nullptr, nullptr, nullptr,
        nullptr, 1.0f, KSPLIT, NPIX, NPIX, NPIX, sCN, sNN, sCN);

    // 6. proj: 8-warp config, B computed in-loader; fp32 out + bias + residual
    dim3 gprj(NPIX/128, CH/128, BATCH);
    mma_gemm<0,2,0,2,4><<<gprj, 256, SM_PRJ>>>(
        p_wpb, nullptr, bp, out, nullptr, nullptr, nullptr,
        x, 1.0f, CH, CH, NPIX, NPIX, 0, sCN, sCN);
}

// round 16
// speedup vs baseline: 1.0008x; 1.0008x over previous
#include <cuda_runtime.h>
#include <cuda_bf16.h>
#include <cstdint>
#include <math.h>

#define BATCH 2
#define CH    256
#define NPIX  4096
#define NGRP  32
#define CPG   (CH/NGRP)
#define GN_EPS 1e-6f
#define QSCALE 0.0625f
#define KSPLIT 2048      // PV split-K half

// ---------------- scratch (static device globals; no allocation) ----------------
__device__ __align__(256) __nv_bfloat16 g_sb[(size_t)BATCH*NPIX*NPIX]; // exp-scores bf16
__device__ __align__(256) __nv_bfloat16 g_qb[BATCH*CH*NPIX];
__device__ __align__(256) __nv_bfloat16 g_kb[BATCH*CH*NPIX];
__device__ __align__(256) __nv_bfloat16 g_vb[BATCH*CH*NPIX];
__device__ __align__(256) float         g_pv[(size_t)BATCH*2*CH*NPIX]; // PV fp32 partials
__device__ __align__(256) float         g_psum[(size_t)BATCH*NPIX*32]; // row partial sums
__device__ __align__(256) float         g_rinv[BATCH*NPIX];            // 1/rowsum
__device__ __align__(256) float         g_gnp[BATCH*CH*2];             // GN per-channel stats
__device__ __align__(256) float         g_ga[BATCH*CH];                // GN apply coeffs
__device__ __align__(256) float         g_be[BATCH*CH];
__device__ __align__(256) __nv_bfloat16 g_wb[3*CH*CH];   // stacked wq,wk,wv bf16
__device__ __align__(256) __nv_bfloat16 g_wpb[CH*CH];
__device__ __align__(256) float         g_bias[3*CH];    // stacked bq,bk,bv

// ---------------- PTX helpers ----------------
__device__ __forceinline__ uint32_t cvta_smem(const void* p) {
    uint32_t a;
    asm("{ .reg .u64 t; cvta.to.shared.u64 t, %1; cvt.u32.u64 %0, t; }" : "=r"(a) : "l"(p));
    return a;
}
__device__ __forceinline__ void cp16(uint32_t s, const void* g) {
    asm volatile("cp.async.cg.shared.global [%0], [%1], 16;" :: "r"(s), "l"(g) : "memory");
}
__device__ __forceinline__ void cp_commit() { asm volatile("cp.async.commit_group;" ::: "memory"); }
template<int N> __device__ __forceinline__ void cp_wait() {
    asm volatile("cp.async.wait_group %0;" :: "n"(N) : "memory");
}
__device__ __forceinline__ void sts128(uint32_t a, uint4 v) {
    asm volatile("st.shared.v4.b32 [%0], {%1,%2,%3,%4};"
                 :: "r"(a), "r"(v.x), "r"(v.y), "r"(v.z), "r"(v.w) : "memory");
}
__device__ __forceinline__ void ldsm4(uint32_t& r0, uint32_t& r1, uint32_t& r2, uint32_t& r3, uint32_t a) {
    asm volatile("ldmatrix.sync.aligned.m8n8.x4.shared.b16 {%0,%1,%2,%3}, [%4];"
                 : "=r"(r0), "=r"(r1), "=r"(r2), "=r"(r3) : "r"(a));
}
__device__ __forceinline__ void ldsm4t(uint32_t& r0, uint32_t& r1, uint32_t& r2, uint32_t& r3, uint32_t a) {
    asm volatile("ldmatrix.sync.aligned.m8n8.x4.trans.shared.b16 {%0,%1,%2,%3}, [%4];"
                 : "=r"(r0), "=r"(r1), "=r"(r2), "=r"(r3) : "r"(a));
}
#define MMA_OP(d, a0,a1,a2,a3, b0,b1) \
    asm volatile("mma.sync.aligned.m16n8k16.row.col.f32.bf16.bf16.f32 " \
                 "{%0,%1,%2,%3}, {%4,%5,%6,%7}, {%8,%9}, {%0,%1,%2,%3};" \
                 : "+f"((d)[0]), "+f"((d)[1]), "+f"((d)[2]), "+f"((d)[3]) \
                 : "r"(a0), "r"(a1), "r"(a2), "r"(a3), "r"(b0), "r"(b1))

__device__ __forceinline__ __nv_bfloat162 pack_bf2(float v0, float v1) {
    __nv_bfloat162 r;
    r.x = __float2bfloat16(v0);
    r.y = __float2bfloat16(v1);
    return r;
}

// ================= bf16 mma.sync GEMM (fp32 accum), BK=64 =================
// 128x128 tile, 8 warps (2x4, warp tile 64x32), STAGES-deep cp.async pipeline.
// ALAY: 0 = A[m*lda+k], 1 = A[k*lda+m] (trans)
// BLAY: 0 = B[n*ldb+k], 1 = B[k*ldb+n] (trans),
//       2 = computed bf16((pv0+pv1)*rinv) (trans), 3 = computed bf16(x*ga+be) (trans, GN fused)
// EPI : 0 fp32 +bias+resid; 1 bf16; 2 fused qkv route; 3 split-K fp32 partial; 4 exp+rowsums
template<int ALAY, int BLAY, int EPI, int STAGES>
__global__ __launch_bounds__(256, 2)
void mma_gemm(const __nv_bfloat16* __restrict__ A, const __nv_bfloat16* __restrict__ B,
              const float* __restrict__ bias, float* __restrict__ OutF,
              __nv_bfloat16* __restrict__ O0, __nv_bfloat16* __restrict__ O1,
              __nv_bfloat16* __restrict__ O2,
              const float* __restrict__ R, float scale,
              int K, int lda, int ldb, int ldo,
              size_t sA, size_t sB, size_t sO)
{
    constexpr uint32_t ASZ = (ALAY == 0) ? 128u*144u : 64u*272u;
    constexpr uint32_t BSZ = (BLAY == 0) ? 128u*144u : 64u*272u;

    extern __shared__ char smem[];
    const uint32_t sbase = cvta_smem(smem);

    const int bz = blockIdx.z;
    const int b  = (EPI == 3) ? (bz >> 1) : bz;
    A += (size_t)b * sA;
    if (BLAY == 0 || BLAY == 1) B += (size_t)b * sB;
    if (EPI == 0) { OutF += (size_t)b * sO; R += (size_t)b * sO; }
    else if (EPI == 1 || EPI == 4) O0 += (size_t)b * sO;
    else if (EPI == 2) { O0 += (size_t)b * sO; O1 += (size_t)b * sO; O2 += (size_t)b * sO; }
    else {
        const int sp = bz & 1;
        A += (size_t)sp * KSPLIT;
        B += (size_t)sp * KSPLIT;
        OutF += (size_t)bz * sO;
    }

    const int tid  = threadIdx.x;
    const int lane = tid & 31;
    const int wid  = tid >> 5;
    const int wm   = wid >> 2;
    const int wn   = wid & 3;
    const int m0   = blockIdx.y * 128;
    const int n0   = blockIdx.x * 128;

    float acc[4][4][4];
    #pragma unroll
    for (int a = 0; a < 4; a++)
        #pragma unroll
        for (int bb2 = 0; bb2 < 4; bb2++)
            #pragma unroll
            for (int c = 0; c < 4; c++) acc[a][bb2][c] = 0.f;

    const int S = K / 64;

    auto load_stage = [&](int s, int slot) {
        const int k0 = s * 64;
        const uint32_t ab = sbase + (uint32_t)slot * (ASZ + BSZ);
        const uint32_t bb = ab + ASZ;
        #pragma unroll
        for (int r = 0; r < 4; r++) {
            const int id = tid + 256 * r;
            if (ALAY == 0) {
                int row = id >> 3, c = id & 7;
                cp16(ab + (uint32_t)row*144u + (uint32_t)c*16u,
                     A + (size_t)(m0 + row)*lda + k0 + c*8);
            } else {
                int row = id >> 4, c = id & 15;
                cp16(ab + (uint32_t)row*272u + (uint32_t)c*16u,
                     A + (size_t)(k0 + row)*lda + m0 + c*8);
            }
            if (BLAY == 0) {
                int row = id >> 3, c = id & 7;
                cp16(bb + (uint32_t)row*144u + (uint32_t)c*16u,
                     B + (size_t)(n0 + row)*ldb + k0 + c*8);
            } else if (BLAY == 1) {
                int row = id >> 4, c = id & 15;
                cp16(bb + (uint32_t)row*272u + (uint32_t)c*16u,
                     B + (size_t)(k0 + row)*ldb + n0 + c*8);
            } else if (BLAY == 2) { // bf16((pv0+pv1)*rinv) -> trans smem
                int row = id >> 4, c = id & 15;
                const size_t sCN_ = (size_t)CH * NPIX;
                const float* p0 = &g_pv[((size_t)b*2 + 0)*sCN_ + (size_t)(k0 + row)*NPIX + n0 + c*8];
                const float* p1 = p0 + sCN_;
                float4 x0 = *(const float4*)p0, x1 = *(const float4*)(p0 + 4);
                float4 y0 = *(const float4*)p1, y1 = *(const float4*)(p1 + 4);
                const float* rp = &g_rinv[b*NPIX + n0 + c*8];
                float4 r0 = *(const float4*)rp, r1 = *(const float4*)(rp + 4);
                __nv_bfloat162 h0 = pack_bf2((x0.x + y0.x)*r0.x, (x0.y + y0.y)*r0.y);
                __nv_bfloat162 h1 = pack_bf2((x0.z + y0.z)*r0.z, (x0.w + y0.w)*r0.w);
                __nv_bfloat162 h2 = pack_bf2((x1.x + y1.x)*r1.x, (x1.y + y1.y)*r1.y);
                __nv_bfloat162 h3 = pack_bf2((x1.z + y1.z)*r1.z, (x1.w + y1.w)*r1.w);
                uint4 u;
                u.x = *(const uint32_t*)&h0; u.y = *(const uint32_t*)&h1;
                u.z = *(const uint32_t*)&h2; u.w = *(const uint32_t*)&h3;
                sts128(bb + (uint32_t)row*272u + (uint32_t)c*16u, u);
            } else { // BLAY == 3: GN fused: bf16(x*ga+be) -> trans smem (x passed via R)
                int row = id >> 4, c = id & 15;
                const int ch = k0 + row;
                const float* xp = R + ((size_t)b*CH + ch)*NPIX + n0 + c*8;
                float4 x0 = *(const float4*)xp, x1 = *(const float4*)(xp + 4);
                const float ga = g_ga[b*CH + ch], be = g_be[b*CH + ch];
                __nv_bfloat162 h0 = pack_bf2(x0.x*ga + be, x0.y*ga + be);
                __nv_bfloat162 h1 = pack_bf2(x0.z*ga + be, x0.w*ga + be);
                __nv_bfloat162 h2 = pack_bf2(x1.x*ga + be, x1.y*ga + be);
                __nv_bfloat162 h3 = pack_bf2(x1.z*ga + be, x1.w*ga + be);
                uint4 u;
                u.x = *(const uint32_t*)&h0; u.y = *(const uint32_t*)&h1;
                u.z = *(const uint32_t*)&h2; u.w = *(const uint32_t*)&h3;
                sts128(bb + (uint32_t)row*272u + (uint32_t)c*16u, u);
            }
        }
        cp_commit();
    };

    const int g4   = lane >> 3;
    const int lr8  = lane & 7;
    const int at_k = lr8 + (g4 & 1) * 8;
    const int at_m = (g4 >> 1) * 8;
    const int ap_r = lane & 15;
    const int ap_c = lane >> 4;
    const int b_kh = (lane >> 3) & 1;
    const int b_nh = (lane >> 4);

    const int pre = (S < STAGES - 1) ? S : (STAGES - 1);
    for (int p = 0; p < pre; p++) load_stage(p, p);

    for (int s = 0; s < S; s++) {
        cp_wait<STAGES - 2>();
        __syncthreads();
        if (s + STAGES - 1 < S) load_stage(s + STAGES - 1, (s + STAGES - 1) % STAGES);

        const uint32_t ab = sbase + (uint32_t)(s % STAGES) * (ASZ + BSZ);
        const uint32_t bb = ab + ASZ;

        #pragma unroll
        for (int kk = 0; kk < 4; kk++) {      // 4 x k16 = BK 64
            uint32_t A0[4], A1[4], A2[4], A3[4];
            #pragma unroll
            for (int mi = 0; mi < 4; mi++) {
                uint32_t r0, r1, r2, r3, addr;
                if (ALAY == 0) {
                    addr = ab + (uint32_t)(wm*64 + mi*16 + ap_r)*144u
                              + (uint32_t)(kk*32 + ap_c*16);
                    ldsm4(r0, r1, r2, r3, addr);
                    A0[mi] = r0; A1[mi] = r1; A2[mi] = r2; A3[mi] = r3;
                } else {
                    addr = ab + (uint32_t)(kk*16 + at_k)*272u
                              + (uint32_t)(wm*64 + mi*16 + at_m)*2u;
                    ldsm4t(r0, r1, r2, r3, addr);
                    A0[mi] = r0; A1[mi] = r2; A2[mi] = r1; A3[mi] = r3;
                }
            }
            uint32_t B0[4], B1[4];
            #pragma unroll
            for (int np = 0; np < 2; np++) {
                uint32_t r0, r1, r2, r3, addr;
                if (BLAY == 0) {
                    int nrow = wn*32 + np*16 + b_nh*8 + lr8;
                    int col  = kk*32 + b_kh*16;
                    addr = bb + (uint32_t)nrow*144u + (uint32_t)col;
                    ldsm4(r0, r1, r2, r3, addr);
                } else {
                    int krow = kk*16 + b_kh*8 + lr8;
                    int ncol = wn*32 + np*16 + b_nh*8;
                    addr = bb + (uint32_t)krow*272u + (uint32_t)ncol*2u;
                    ldsm4t(r0, r1, r2, r3, addr);
                }
                B0[2*np]   = r0; B1[2*np]   = r1;
                B0[2*np+1] = r2; B1[2*np+1] = r3;
            }
            #pragma unroll
            for (int mi = 0; mi < 4; mi++)
                #pragma unroll
                for (int ni = 0; ni < 4; ni++)
                    MMA_OP(acc[mi][ni], A0[mi], A1[mi], A2[mi], A3[mi], B0[ni], B1[ni]);
        }
    }

    // ---------------- epilogue ----------------
    const int em = (lane >> 2);
    const int en = (lane & 3) * 2;
    const int seg = m0 >> 8;
    __nv_bfloat16* Oseg = (EPI == 2) ? (seg == 0 ? O0 : (seg == 1 ? O1 : O2)) : O0;
    const float segscale = (EPI == 2) ? (seg == 0 ? QSCALE : 1.0f) : scale;

    float* rowpart = (float*)smem;
    if (EPI == 4) __syncthreads();

    #pragma unroll
    for (int mi = 0; mi < 4; mi++) {
        const int mA = m0 + wm*64 + mi*16 + em;
        const int mB = mA + 8;
        float sA_ = 0.f, sB_ = 0.f;
        #pragma unroll
        for (int ni = 0; ni < 4; ni++) {
            const int n = n0 + wn*32 + ni*8 + en;
            float* d = acc[mi][ni];
            if (EPI == 0) {
                const float bvA = bias[mA], bvB = bias[mB];
                float2 oA = { (d[0] + bvA)*scale, (d[1] + bvA)*scale };
                float2 oB = { (d[2] + bvB)*scale, (d[3] + bvB)*scale };
                float2 rA = *(const float2*)&R[(size_t)mA*ldo + n];
                float2 rB = *(const float2*)&R[(size_t)mB*ldo + n];
                oA.x += rA.x; oA.y += rA.y; oB.x += rB.x; oB.y += rB.y;
                *(float2*)&OutF[(size_t)mA*ldo + n] = oA;
                *(float2*)&OutF[(size_t)mB*ldo + n] = oB;
            } else if (EPI == 1) {
                *(__nv_bfloat162*)&O0[(size_t)mA*ldo + n] = pack_bf2(d[0]*scale, d[1]*scale);
                *(__nv_bfloat162*)&O0[(size_t)mB*ldo + n] = pack_bf2(d[2]*scale, d[3]*scale);
            } else if (EPI == 2) {
                const float bvA = bias[mA], bvB = bias[mB];
                const int rA = mA & 255, rB = mB & 255;
                *(__nv_bfloat162*)&Oseg[(size_t)rA*ldo + n] =
                    pack_bf2((d[0] + bvA)*segscale, (d[1] + bvA)*segscale);
                *(__nv_bfloat162*)&Oseg[(size_t)rB*ldo + n] =
                    pack_bf2((d[2] + bvB)*segscale, (d[3] + bvB)*segscale);
            } else if (EPI == 3) {
                float2 oA = { d[0], d[1] };
                float2 oB = { d[2], d[3] };
                *(float2*)&OutF[(size_t)mA*ldo + n] = oA;
                *(float2*)&OutF[(size_t)mB*ldo + n] = oB;
            } else {
                float e0 = __expf(d[0]), e1 = __expf(d[1]);
                float e2 = __expf(d[2]), e3 = __expf(d[3]);
                *(__nv_bfloat162*)&O0[(size_t)mA*ldo + n] = pack_bf2(e0, e1);
                *(__nv_bfloat162*)&O0[(size_t)mB*ldo + n] = pack_bf2(e2, e3);
                sA_ += e0 + e1;
                sB_ += e2 + e3;
            }
        }
        if (EPI == 4) {
            sA_ += __shfl_xor_sync(0xFFFFFFFFu, sA_, 1);
            sA_ += __shfl_xor_sync(0xFFFFFFFFu, sA_, 2);
            sB_ += __shfl_xor_sync(0xFFFFFFFFu, sB_, 1);
            sB_ += __shfl_xor_sync(0xFFFFFFFFu, sB_, 2);
            if ((lane & 3) == 0) {
                rowpart[wn*128 + (wm*64 + mi*16 + em)]     = sA_;
                rowpart[wn*128 + (wm*64 + mi*16 + em + 8)] = sB_;
            }
        }
    }
    if (EPI == 4) {
        __syncthreads();
        if (tid < 128) {
            float s = rowpart[tid] + rowpart[128 + tid]
                    + rowpart[256 + tid] + rowpart[384 + tid];
            g_psum[((size_t)b*NPIX + m0 + tid)*32 + blockIdx.x] = s;
        }
    }
}

// ---------------- row sums -> 1/sum ----------------
__global__ void rowsum_kernel() {
    const int r = blockIdx.x * 256 + threadIdx.x;
    const float4* p = (const float4*)&g_psum[(size_t)r * 32];
    float s = 0.f;
    #pragma unroll
    for (int i = 0; i < 8; i++) {
        float4 v = p[i];
        s += v.x + v.y + v.z + v.w;
    }
    g_rinv[r] = 1.0f / s;
}

// ---------------- prep: stack + convert weights/biases ----------------
__global__ void prep_kernel(const float* __restrict__ wq, const float* __restrict__ wk,
                            const float* __restrict__ wv, const float* __restrict__ wp,
                            const float* __restrict__ bq, const float* __restrict__ bk,
                            const float* __restrict__ bv) {
    int i = blockIdx.x * 256 + threadIdx.x;
    if (i < 3*CH*CH) {
        int r = i / CH;
        int seg = r >> 8;
        const float* w = seg == 0 ? wq : (seg == 1 ? wk : wv);
        g_wb[i] = __float2bfloat16(w[(size_t)(r & 255)*CH + (i % CH)]);
    } else if (i < 4*CH*CH) {
        int j = i - 3*CH*CH;
        g_wpb[j] = __float2bfloat16(wp[j]);
    } else if (i < 4*CH*CH + 3*CH) {
        int j = i - 4*CH*CH;
        int seg = j >> 8;
        const float* bb = seg == 0 ? bq : (seg == 1 ? bk : bv);
        g_bias[j] = bb[j & 255];
    }
}

// ---------------- GroupNorm phase 1: per-channel partial sums ----------------
// grid = BATCH*CH (one CTA per (b,channel))
__global__ void gn_stats(const float* __restrict__ x) {
    const int id = blockIdx.x;
    const size_t base = (size_t)id * NPIX;
    const float4* xp4 = (const float4*)(x + base);
    const int tid = threadIdx.x;
    float s = 0.f, s2 = 0.f;
    #pragma unroll
    for (int i = 0; i < 4; i++) {
        float4 v = xp4[tid + 256*i];
        s  += v.x + v.y + v.z + v.w;
        s2 += v.x*v.x + v.y*v.y + v.z*v.z + v.w*v.w;
    }
    __shared__ float sh[256], sh2[256];
    sh[tid] = s; sh2[tid] = s2;
    __syncthreads();
    for (int o = 128; o > 0; o >>= 1) {
        if (tid < o) { sh[tid] += sh[tid+o]; sh2[tid] += sh2[tid+o]; }
        __syncthreads();
    }
    if (tid == 0) {
        g_gnp[id*2]     = sh[0];
        g_gnp[id*2 + 1] = sh2[0];
    }
}

// ---------------- GroupNorm phase 2: finalize coefficients (ga, be) ----------------
// grid = BATCH, 256 threads: one thread per channel
__global__ void gn_coef(const float* __restrict__ gamma, const float* __restrict__ beta) {
    const int b  = blockIdx.x;
    const int ch = threadIdx.x;
    const int g  = ch >> 3;            // group (CPG = 8)
    float s = 0.f, s2 = 0.f;
    #pragma unroll
    for (int k = 0; k < 8; k++) {
        s  += g_gnp[(b*CH + g*8 + k)*2];
        s2 += g_gnp[(b*CH + g*8 + k)*2 + 1];
    }
    const float inv_n = 1.0f / (float)(CPG*NPIX);
    const float mean  = s * inv_n;
    const float var   = s2 * inv_n - mean*mean;
    const float rstd  = rsqrtf(var + GN_EPS);
    const float ga = gamma[ch] * rstd;
    g_ga[b*CH + ch] = ga;
    g_be[b*CH + ch] = beta[ch] - mean * ga;
}

// ---------------- launch ----------------
extern "C" void kernel_launch(void* const* d_in, const int* in_sizes, int n_in,
                              void* d_out, int out_size) {
    const float* x     = (const float*)d_in[0];
    const float* gamma = (const float*)d_in[1];
    const float* beta  = (const float*)d_in[2];
    const float* wq = (const float*)d_in[3];
    const float* bq = (const float*)d_in[4];
    const float* wk = (const float*)d_in[5];
    const float* bk = (const float*)d_in[6];
    const float* wv = (const float*)d_in[7];
    const float* bv = (const float*)d_in[8];
    const float* wp = (const float*)d_in[9];
    const float* bp = (const float*)d_in[10];
    float* out = (float*)d_out;

    __nv_bfloat16 *p_sb, *p_qb, *p_kb, *p_vb, *p_wb, *p_wpb;
    float *p_bias, *p_pv;
    cudaGetSymbolAddress((void**)&p_sb,  g_sb);
    cudaGetSymbolAddress((void**)&p_qb,  g_qb);
    cudaGetSymbolAddress((void**)&p_kb,  g_kb);
    cudaGetSymbolAddress((void**)&p_vb,  g_vb);
    cudaGetSymbolAddress((void**)&p_wb,  g_wb);
    cudaGetSymbolAddress((void**)&p_wpb, g_wpb);
    cudaGetSymbolAddress((void**)&p_bias, g_bias);
    cudaGetSymbolAddress((void**)&p_pv,  g_pv);

    // smem per stage (BK=64): plain = 128*144 = 18432, trans = 64*272 = 17408
    const int SM_QKV = 2 * (18432 + 17408);   // A plain, B computed-trans (GN) = 71680
    const int SM_SCO = 2 * (17408 + 17408);   // both trans                     = 69632
    const int SM_PV  = 2 * (18432 + 18432);   // both plain                     = 73728
    const int SM_PRJ = 2 * (18432 + 17408);   // A plain, B computed-trans      = 71680
    cudaFuncSetAttribute(mma_gemm<0,3,2,2>, cudaFuncAttributeMaxDynamicSharedMemorySize, SM_QKV);
    cudaFuncSetAttribute(mma_gemm<1,1,4,2>, cudaFuncAttributeMaxDynamicSharedMemorySize, SM_SCO);
    cudaFuncSetAttribute(mma_gemm<0,0,3,2>, cudaFuncAttributeMaxDynamicSharedMemorySize, SM_PV);
    cudaFuncSetAttribute(mma_gemm<0,2,0,2>, cudaFuncAttributeMaxDynamicSharedMemorySize, SM_PRJ);

    const size_t sCN = (size_t)CH * NPIX;
    const size_t sNN = (size_t)NPIX * NPIX;

    // 0. prep weights/biases
    prep_kernel<<<(4*CH*CH + 3*CH + 255)/256, 256>>>(wq, wk, wv, wp, bq, bk, bv);

    // 1. GroupNorm stats + coefficients (apply is fused into qkv's B loader)
    gn_stats<<<BATCH*CH, 256>>>(x);
    gn_coef<<<BATCH, 256>>>(gamma, beta);

    // 2. fused qkv: A = stacked W plain; B = bf16(x*ga+be) computed in-loader (x via R)
    dim3 gqkv(NPIX/128, (3*CH)/128, BATCH);
    mma_gemm<0,3,2,2><<<gqkv, 256, SM_QKV>>>(
        p_wb, nullptr, p_bias, nullptr, p_qb, p_kb, p_vb,
        x, 1.0f, CH, CH, NPIX, NPIX, 0, sCN, sCN);

    // 3. exp-scores = exp(q^T k) + row partial sums
    dim3 gsc(NPIX/128, NPIX/128, BATCH);
    mma_gemm<1,1,4,2><<<gsc, 256, SM_SCO>>>(
        p_qb, p_kb, nullptr, nullptr, p_sb, nullptr, nullptr,
        nullptr, 1.0f, CH, NPIX, NPIX, NPIX, sCN, sCN, sNN);

    // 4. row sums -> 1/sum
    rowsum_kernel<<<BATCH*NPIX/256, 256>>>();

    // 5. PV split-K=2 on unnormalized exp-scores: fp32 partials
    dim3 gpv(NPIX/128, CH/128, BATCH*2);
    mma_gemm<0,0,3,2><<<gpv, 256, SM_PV>>>(
        p_vb, p_sb, nullptr, p_pv, nullptr, nullptr, nullptr,
        nullptr, 1.0f, KSPLIT, NPIX, NPIX, NPIX, sCN, sNN, sCN);

    // 6. proj: A = Wp plain, B = bf16((pv0+pv1)*rinv) in-loader; fp32 out + bias + residual
    dim3 gprj(NPIX/128, CH/128, BATCH);
    mma_gemm<0,2,0,2><<<gprj, 256, SM_PRJ>>>(
        p_wpb, nullptr, bp, out, nullptr, nullptr, nullptr,
        x, 1.0f, CH, CH, NPIX, NPIX, 0, sCN, sCN);
}

// round 17
// speedup vs baseline: 1.0348x; 1.0339x over previous
#include <cuda_runtime.h>
#include <cuda_bf16.h>
#include <cstdint>
#include <math.h>

#define BATCH 2
#define CH    256
#define NPIX  4096
#define NGRP  32
#define CPG   (CH/NGRP)
#define GN_EPS 1e-6f
#define QSCALE 0.0625f
#define KSPLIT 2048      // PV split-K half

// ---------------- scratch (static device globals; no allocation) ----------------
__device__ __align__(256) __nv_bfloat16 g_sb[(size_t)BATCH*NPIX*NPIX]; // exp-scores bf16
__device__ __align__(256) __nv_bfloat16 g_hb[BATCH*CH*NPIX];
__device__ __align__(256) __nv_bfloat16 g_qb[BATCH*CH*NPIX];
__device__ __align__(256) __nv_bfloat16 g_kb[BATCH*CH*NPIX];
__device__ __align__(256) __nv_bfloat16 g_vb[BATCH*CH*NPIX];
__device__ __align__(256) __nv_bfloat16 g_pvb[(size_t)BATCH*2*CH*NPIX]; // PV bf16 partials
__device__ __align__(256) float         g_psum[(size_t)BATCH*NPIX*32]; // row partial sums
__device__ __align__(256) float         g_rinv[BATCH*NPIX];            // 1/rowsum
__device__ __align__(256) float         g_gnp[BATCH*CH*2];             // GN per-channel stats
__device__ __align__(256) __nv_bfloat16 g_wb[3*CH*CH];   // stacked wq,wk,wv bf16
__device__ __align__(256) __nv_bfloat16 g_wpb[CH*CH];
__device__ __align__(256) float         g_bias[3*CH];    // stacked bq,bk,bv

// ---------------- PTX helpers ----------------
__device__ __forceinline__ uint32_t cvta_smem(const void* p) {
    uint32_t a;
    asm("{ .reg .u64 t; cvta.to.shared.u64 t, %1; cvt.u32.u64 %0, t; }" : "=r"(a) : "l"(p));
    return a;
}
__device__ __forceinline__ void cp16(uint32_t s, const void* g) {
    asm volatile("cp.async.cg.shared.global [%0], [%1], 16;" :: "r"(s), "l"(g) : "memory");
}
__device__ __forceinline__ void cp_commit() { asm volatile("cp.async.commit_group;" ::: "memory"); }
template<int N> __device__ __forceinline__ void cp_wait() {
    asm volatile("cp.async.wait_group %0;" :: "n"(N) : "memory");
}
__device__ __forceinline__ void sts128(uint32_t a, uint4 v) {
    asm volatile("st.shared.v4.b32 [%0], {%1,%2,%3,%4};"
                 :: "r"(a), "r"(v.x), "r"(v.y), "r"(v.z), "r"(v.w) : "memory");
}
__device__ __forceinline__ void ldsm4(uint32_t& r0, uint32_t& r1, uint32_t& r2, uint32_t& r3, uint32_t a) {
    asm volatile("ldmatrix.sync.aligned.m8n8.x4.shared.b16 {%0,%1,%2,%3}, [%4];"
                 : "=r"(r0), "=r"(r1), "=r"(r2), "=r"(r3) : "r"(a));
}
__device__ __forceinline__ void ldsm4t(uint32_t& r0, uint32_t& r1, uint32_t& r2, uint32_t& r3, uint32_t a) {
    asm volatile("ldmatrix.sync.aligned.m8n8.x4.trans.shared.b16 {%0,%1,%2,%3}, [%4];"
                 : "=r"(r0), "=r"(r1), "=r"(r2), "=r"(r3) : "r"(a));
}
#define MMA_OP(d, a0,a1,a2,a3, b0,b1) \
    asm volatile("mma.sync.aligned.m16n8k16.row.col.f32.bf16.bf16.f32 " \
                 "{%0,%1,%2,%3}, {%4,%5,%6,%7}, {%8,%9}, {%0,%1,%2,%3};" \
                 : "+f"((d)[0]), "+f"((d)[1]), "+f"((d)[2]), "+f"((d)[3]) \
                 : "r"(a0), "r"(a1), "r"(a2), "r"(a3), "r"(b0), "r"(b1))

__device__ __forceinline__ __nv_bfloat162 pack_bf2(float v0, float v1) {
    __nv_bfloat162 r;
    r.x = __float2bfloat16(v0);
    r.y = __float2bfloat16(v1);
    return r;
}
__device__ __forceinline__ float2 unpack_bf2(uint32_t w) {
    __nv_bfloat162 b = *(const __nv_bfloat162*)&w;
    return make_float2(__bfloat162float(b.x), __bfloat162float(b.y));
}

// ================= bf16 mma.sync GEMM (fp32 accum), BK=64 =================
// 128x128 tile, 8 warps (2x4, warp tile 64x32), STAGES-deep cp.async pipeline.
// ALAY: 0 = A[m*lda+k], 1 = A[k*lda+m] (trans)
// BLAY: 0 = B[n*ldb+k], 1 = B[k*ldb+n] (trans),
//       2 = computed bf16((pv0+pv1)*rinv) from bf16 partials (trans)
// EPI : 0 fp32 +bias+resid; 1 bf16; 2 fused qkv route; 3 split-K bf16 partial; 4 exp+rowsums
template<int ALAY, int BLAY, int EPI, int STAGES>
__global__ __launch_bounds__(256, 2)
void mma_gemm(const __nv_bfloat16* __restrict__ A, const __nv_bfloat16* __restrict__ B,
              const float* __restrict__ bias, float* __restrict__ OutF,
              __nv_bfloat16* __restrict__ O0, __nv_bfloat16* __restrict__ O1,
              __nv_bfloat16* __restrict__ O2,
              const float* __restrict__ R, float scale,
              int K, int lda, int ldb, int ldo,
              size_t sA, size_t sB, size_t sO)
{
    constexpr uint32_t ASZ = (ALAY == 0) ? 128u*144u : 64u*272u;
    constexpr uint32_t BSZ = (BLAY == 0) ? 128u*144u : 64u*272u;

    extern __shared__ char smem[];
    const uint32_t sbase = cvta_smem(smem);

    const int bz = blockIdx.z;
    const int b  = (EPI == 3) ? (bz >> 1) : bz;
    A += (size_t)b * sA;
    if (BLAY != 2) B += (size_t)b * sB;
    if (EPI == 0) { OutF += (size_t)b * sO; R += (size_t)b * sO; }
    else if (EPI == 1 || EPI == 4) O0 += (size_t)b * sO;
    else if (EPI == 2) { O0 += (size_t)b * sO; O1 += (size_t)b * sO; O2 += (size_t)b * sO; }
    else { // EPI == 3: split-K bf16 partial
        const int sp = bz & 1;
        A += (size_t)sp * KSPLIT;
        B += (size_t)sp * KSPLIT;
        O0 += (size_t)bz * sO;
    }

    const int tid  = threadIdx.x;
    const int lane = tid & 31;
    const int wid  = tid >> 5;
    const int wm   = wid >> 2;
    const int wn   = wid & 3;
    const int m0   = blockIdx.y * 128;
    const int n0   = blockIdx.x * 128;

    float acc[4][4][4];
    #pragma unroll
    for (int a = 0; a < 4; a++)
        #pragma unroll
        for (int bb2 = 0; bb2 < 4; bb2++)
            #pragma unroll
            for (int c = 0; c < 4; c++) acc[a][bb2][c] = 0.f;

    const int S = K / 64;

    auto load_stage = [&](int s, int slot) {
        const int k0 = s * 64;
        const uint32_t ab = sbase + (uint32_t)slot * (ASZ + BSZ);
        const uint32_t bb = ab + ASZ;
        #pragma unroll
        for (int r = 0; r < 4; r++) {
            const int id = tid + 256 * r;
            if (ALAY == 0) {
                int row = id >> 3, c = id & 7;
                cp16(ab + (uint32_t)row*144u + (uint32_t)c*16u,
                     A + (size_t)(m0 + row)*lda + k0 + c*8);
            } else {
                int row = id >> 4, c = id & 15;
                cp16(ab + (uint32_t)row*272u + (uint32_t)c*16u,
                     A + (size_t)(k0 + row)*lda + m0 + c*8);
            }
            if (BLAY == 0) {
                int row = id >> 3, c = id & 7;
                cp16(bb + (uint32_t)row*144u + (uint32_t)c*16u,
                     B + (size_t)(n0 + row)*ldb + k0 + c*8);
            } else if (BLAY == 1) {
                int row = id >> 4, c = id & 15;
                cp16(bb + (uint32_t)row*272u + (uint32_t)c*16u,
                     B + (size_t)(k0 + row)*ldb + n0 + c*8);
            } else { // BLAY == 2: bf16((pv0+pv1)*rinv) from bf16 partials -> trans smem
                int row = id >> 4, c = id & 15;
                const size_t sCN_ = (size_t)CH * NPIX;
                const __nv_bfloat16* p0 =
                    &g_pvb[((size_t)b*2 + 0)*sCN_ + (size_t)(k0 + row)*NPIX + n0 + c*8];
                const __nv_bfloat16* p1 = p0 + sCN_;
                uint4 u0 = *(const uint4*)p0;
                uint4 u1 = *(const uint4*)p1;
                const float* rp = &g_rinv[b*NPIX + n0 + c*8];
                float4 r0 = *(const float4*)rp, r1 = *(const float4*)(rp + 4);
                float2 a0 = unpack_bf2(u0.x), b0 = unpack_bf2(u1.x);
                float2 a1 = unpack_bf2(u0.y), b1 = unpack_bf2(u1.y);
                float2 a2 = unpack_bf2(u0.z), b2 = unpack_bf2(u1.z);
                float2 a3 = unpack_bf2(u0.w), b3 = unpack_bf2(u1.w);
                __nv_bfloat162 h0 = pack_bf2((a0.x + b0.x)*r0.x, (a0.y + b0.y)*r0.y);
                __nv_bfloat162 h1 = pack_bf2((a1.x + b1.x)*r0.z, (a1.y + b1.y)*r0.w);
                __nv_bfloat162 h2 = pack_bf2((a2.x + b2.x)*r1.x, (a2.y + b2.y)*r1.y);
                __nv_bfloat162 h3 = pack_bf2((a3.x + b3.x)*r1.z, (a3.y + b3.y)*r1.w);
                uint4 u;
                u.x = *(const uint32_t*)&h0; u.y = *(const uint32_t*)&h1;
                u.z = *(const uint32_t*)&h2; u.w = *(const uint32_t*)&h3;
                sts128(bb + (uint32_t)row*272u + (uint32_t)c*16u, u);
            }
        }
        cp_commit();
    };

    const int g4   = lane >> 3;
    const int lr8  = lane & 7;
    const int at_k = lr8 + (g4 & 1) * 8;
    const int at_m = (g4 >> 1) * 8;
    const int ap_r = lane & 15;
    const int ap_c = lane >> 4;
    const int b_kh = (lane >> 3) & 1;
    const int b_nh = (lane >> 4);

    const int pre = (S < STAGES - 1) ? S : (STAGES - 1);
    for (int p = 0; p < pre; p++) load_stage(p, p);

    for (int s = 0; s < S; s++) {
        cp_wait<STAGES - 2>();
        __syncthreads();
        if (s + STAGES - 1 < S) load_stage(s + STAGES - 1, (s + STAGES - 1) % STAGES);

        const uint32_t ab = sbase + (uint32_t)(s % STAGES) * (ASZ + BSZ);
        const uint32_t bb = ab + ASZ;

        #pragma unroll
        for (int kk = 0; kk < 4; kk++) {      // 4 x k16 = BK 64
            uint32_t A0[4], A1[4], A2[4], A3[4];
            #pragma unroll
            for (int mi = 0; mi < 4; mi++) {
                uint32_t r0, r1, r2, r3, addr;
                if (ALAY == 0) {
                    addr = ab + (uint32_t)(wm*64 + mi*16 + ap_r)*144u
                              + (uint32_t)(kk*32 + ap_c*16);
                    ldsm4(r0, r1, r2, r3, addr);
                    A0[mi] = r0; A1[mi] = r1; A2[mi] = r2; A3[mi] = r3;
                } else {
                    addr = ab + (uint32_t)(kk*16 + at_k)*272u
                              + (uint32_t)(wm*64 + mi*16 + at_m)*2u;
                    ldsm4t(r0, r1, r2, r3, addr);
                    A0[mi] = r0; A1[mi] = r2; A2[mi] = r1; A3[mi] = r3;
                }
            }
            uint32_t B0[4], B1[4];
            #pragma unroll
            for (int np = 0; np < 2; np++) {
                uint32_t r0, r1, r2, r3, addr;
                if (BLAY == 0) {
                    int nrow = wn*32 + np*16 + b_nh*8 + lr8;
                    int col  = kk*32 + b_kh*16;
                    addr = bb + (uint32_t)nrow*144u + (uint32_t)col;
                    ldsm4(r0, r1, r2, r3, addr);
                } else {
                    int krow = kk*16 + b_kh*8 + lr8;
                    int ncol = wn*32 + np*16 + b_nh*8;
                    addr = bb + (uint32_t)krow*272u + (uint32_t)ncol*2u;
                    ldsm4t(r0, r1, r2, r3, addr);
                }
                B0[2*np]   = r0; B1[2*np]   = r1;
                B0[2*np+1] = r2; B1[2*np+1] = r3;
            }
            #pragma unroll
            for (int mi = 0; mi < 4; mi++)
                #pragma unroll
                for (int ni = 0; ni < 4; ni++)
                    MMA_OP(acc[mi][ni], A0[mi], A1[mi], A2[mi], A3[mi], B0[ni], B1[ni]);
        }
    }

    // ---------------- epilogue ----------------
    const int em = (lane >> 2);
    const int en = (lane & 3) * 2;
    const int seg = m0 >> 8;
    __nv_bfloat16* Oseg = (EPI == 2) ? (seg == 0 ? O0 : (seg == 1 ? O1 : O2)) : O0;
    const float segscale = (EPI == 2) ? (seg == 0 ? QSCALE : 1.0f) : scale;

    float* rowpart = (float*)smem;
    if (EPI == 4) __syncthreads();

    #pragma unroll
    for (int mi = 0; mi < 4; mi++) {
        const int mA = m0 + wm*64 + mi*16 + em;
        const int mB = mA + 8;
        float sA_ = 0.f, sB_ = 0.f;
        #pragma unroll
        for (int ni = 0; ni < 4; ni++) {
            const int n = n0 + wn*32 + ni*8 + en;
            float* d = acc[mi][ni];
            if (EPI == 0) {
                const float bvA = bias[mA], bvB = bias[mB];
                float2 oA = { (d[0] + bvA)*scale, (d[1] + bvA)*scale };
                float2 oB = { (d[2] + bvB)*scale, (d[3] + bvB)*scale };
                float2 rA = *(const float2*)&R[(size_t)mA*ldo + n];
                float2 rB = *(const float2*)&R[(size_t)mB*ldo + n];
                oA.x += rA.x; oA.y += rA.y; oB.x += rB.x; oB.y += rB.y;
                *(float2*)&OutF[(size_t)mA*ldo + n] = oA;
                *(float2*)&OutF[(size_t)mB*ldo + n] = oB;
            } else if (EPI == 1) {
                *(__nv_bfloat162*)&O0[(size_t)mA*ldo + n] = pack_bf2(d[0]*scale, d[1]*scale);
                *(__nv_bfloat162*)&O0[(size_t)mB*ldo + n] = pack_bf2(d[2]*scale, d[3]*scale);
            } else if (EPI == 2) {
                const float bvA = bias[mA], bvB = bias[mB];
                const int rA = mA & 255, rB = mB & 255;
                *(__nv_bfloat162*)&Oseg[(size_t)rA*ldo + n] =
                    pack_bf2((d[0] + bvA)*segscale, (d[1] + bvA)*segscale);
                *(__nv_bfloat162*)&Oseg[(size_t)rB*ldo + n] =
                    pack_bf2((d[2] + bvB)*segscale, (d[3] + bvB)*segscale);
            } else if (EPI == 3) { // bf16 split-K partial
                *(__nv_bfloat162*)&O0[(size_t)mA*ldo + n] = pack_bf2(d[0], d[1]);
                *(__nv_bfloat162*)&O0[(size_t)mB*ldo + n] = pack_bf2(d[2], d[3]);
            } else { // EPI == 4: exp + partial row sums
                float e0 = __expf(d[0]), e1 = __expf(d[1]);
                float e2 = __expf(d[2]), e3 = __expf(d[3]);
                *(__nv_bfloat162*)&O0[(size_t)mA*ldo + n] = pack_bf2(e0, e1);
                *(__nv_bfloat162*)&O0[(size_t)mB*ldo + n] = pack_bf2(e2, e3);
                sA_ += e0 + e1;
                sB_ += e2 + e3;
            }
        }
        if (EPI == 4) {
            sA_ += __shfl_xor_sync(0xFFFFFFFFu, sA_, 1);
            sA_ += __shfl_xor_sync(0xFFFFFFFFu, sA_, 2);
            sB_ += __shfl_xor_sync(0xFFFFFFFFu, sB_, 1);
            sB_ += __shfl_xor_sync(0xFFFFFFFFu, sB_, 2);
            if ((lane & 3) == 0) {
                rowpart[wn*128 + (wm*64 + mi*16 + em)]     = sA_;
                rowpart[wn*128 + (wm*64 + mi*16 + em + 8)] = sB_;
            }
        }
    }
    if (EPI == 4) {
        __syncthreads();
        if (tid < 128) {
            float s = rowpart[tid] + rowpart[128 + tid]
                    + rowpart[256 + tid] + rowpart[384 + tid];
            g_psum[((size_t)b*NPIX + m0 + tid)*32 + blockIdx.x] = s;
        }
    }
}

// ---------------- row sums -> 1/sum ----------------
__global__ void rowsum_kernel() {
    const int r = blockIdx.x * 256 + threadIdx.x;
    const float4* p = (const float4*)&g_psum[(size_t)r * 32];
    float s = 0.f;
    #pragma unroll
    for (int i = 0; i < 8; i++) {
        float4 v = p[i];
        s += v.x + v.y + v.z + v.w;
    }
    g_rinv[r] = 1.0f / s;
}

// ---------------- prep: stack + convert weights/biases ----------------
__global__ void prep_kernel(const float* __restrict__ wq, const float* __restrict__ wk,
                            const float* __restrict__ wv, const float* __restrict__ wp,
                            const float* __restrict__ bq, const float* __restrict__ bk,
                            const float* __restrict__ bv) {
    int i = blockIdx.x * 256 + threadIdx.x;
    if (i < 3*CH*CH) {
        int r = i / CH;
        int seg = r >> 8;
        const float* w = seg == 0 ? wq : (seg == 1 ? wk : wv);
        g_wb[i] = __float2bfloat16(w[(size_t)(r & 255)*CH + (i % CH)]);
    } else if (i < 4*CH*CH) {
        int j = i - 3*CH*CH;
        g_wpb[j] = __float2bfloat16(wp[j]);
    } else if (i < 4*CH*CH + 3*CH) {
        int j = i - 4*CH*CH;
        int seg = j >> 8;
        const float* bb = seg == 0 ? bq : (seg == 1 ? bk : bv);
        g_bias[j] = bb[j & 255];
    }
}

// ---------------- GroupNorm phase 1: per-channel partial sums ----------------
__global__ void gn_stats(const float* __restrict__ x) {
    const int id = blockIdx.x;
    const size_t base = (size_t)id * NPIX;
    const float4* xp4 = (const float4*)(x + base);
    const int tid = threadIdx.x;
    float s = 0.f, s2 = 0.f;
    #pragma unroll
    for (int i = 0; i < 4; i++) {
        float4 v = xp4[tid + 256*i];
        s  += v.x + v.y + v.z + v.w;
        s2 += v.x*v.x + v.y*v.y + v.z*v.z + v.w*v.w;
    }
    __shared__ float sh[256], sh2[256];
    sh[tid] = s; sh2[tid] = s2;
    __syncthreads();
    for (int o = 128; o > 0; o >>= 1) {
        if (tid < o) { sh[tid] += sh[tid+o]; sh2[tid] += sh2[tid+o]; }
        __syncthreads();
    }
    if (tid == 0) {
        g_gnp[id*2]     = sh[0];
        g_gnp[id*2 + 1] = sh2[0];
    }
}

// ---------------- GroupNorm phase 2: finalize + apply -> bf16 h ----------------
__global__ void gn_apply(const float* __restrict__ x,
                         const float* __restrict__ gamma,
                         const float* __restrict__ beta) {
    const int id = blockIdx.x;           // b*CH + ch
    const int bg = id >> 3;              // group-slice base (CPG=8)
    const int g  = bg % NGRP;
    const int sl = id & 7;
    float s = 0.f, s2 = 0.f;
    #pragma unroll
    for (int k = 0; k < 8; k++) {
        s  += g_gnp[(bg*8 + k)*2];
        s2 += g_gnp[(bg*8 + k)*2 + 1];
    }
    const float inv_n = 1.0f / (float)(CPG*NPIX);
    const float mean  = s * inv_n;
    const float var   = s2 * inv_n - mean*mean;
    const float rstd  = rsqrtf(var + GN_EPS);
    const int ch = g*CPG + sl;
    const float ga = gamma[ch] * rstd;
    const float be = beta[ch] - mean * ga;

    const size_t base = (size_t)id * NPIX;
    const float4* xp4 = (const float4*)(x + base);
    __nv_bfloat162* hb2 = (__nv_bfloat162*)(g_hb + base);
    const int tid = threadIdx.x;
    #pragma unroll
    for (int i = 0; i < 4; i++) {
        float4 v = xp4[tid + 256*i];
        hb2[(tid + 256*i)*2]     = pack_bf2(v.x*ga + be, v.y*ga + be);
        hb2[(tid + 256*i)*2 + 1] = pack_bf2(v.z*ga + be, v.w*ga + be);
    }
}

// ---------------- launch ----------------
extern "C" void kernel_launch(void* const* d_in, const int* in_sizes, int n_in,
                              void* d_out, int out_size) {
    const float* x     = (const float*)d_in[0];
    const float* gamma = (const float*)d_in[1];
    const float* beta  = (const float*)d_in[2];
    const float* wq = (const float*)d_in[3];
    const float* bq = (const float*)d_in[4];
    const float* wk = (const float*)d_in[5];
    const float* bk = (const float*)d_in[6];
    const float* wv = (const float*)d_in[7];
    const float* bv = (const float*)d_in[8];
    const float* wp = (const float*)d_in[9];
    const float* bp = (const float*)d_in[10];
    float* out = (float*)d_out;

    __nv_bfloat16 *p_sb, *p_hb, *p_qb, *p_kb, *p_vb, *p_pvb, *p_wb, *p_wpb;
    float* p_bias;
    cudaGetSymbolAddress((void**)&p_sb,  g_sb);
    cudaGetSymbolAddress((void**)&p_hb,  g_hb);
    cudaGetSymbolAddress((void**)&p_qb,  g_qb);
    cudaGetSymbolAddress((void**)&p_kb,  g_kb);
    cudaGetSymbolAddress((void**)&p_vb,  g_vb);
    cudaGetSymbolAddress((void**)&p_pvb, g_pvb);
    cudaGetSymbolAddress((void**)&p_wb,  g_wb);
    cudaGetSymbolAddress((void**)&p_wpb, g_wpb);
    cudaGetSymbolAddress((void**)&p_bias, g_bias);

    // smem per stage (BK=64): plain = 128*144 = 18432, trans = 64*272 = 17408
    const int SM_QKV = 2 * (18432 + 17408);   // A plain, B trans = 71680
    const int SM_SCO = 2 * (17408 + 17408);   // both trans       = 69632
    const int SM_PV  = 2 * (18432 + 18432);   // both plain       = 73728
    const int SM_PRJ = 2 * (18432 + 17408);   // A plain, B computed-trans = 71680
    cudaFuncSetAttribute(mma_gemm<0,1,2,2>, cudaFuncAttributeMaxDynamicSharedMemorySize, SM_QKV);
    cudaFuncSetAttribute(mma_gemm<1,1,4,2>, cudaFuncAttributeMaxDynamicSharedMemorySize, SM_SCO);
    cudaFuncSetAttribute(mma_gemm<0,0,3,2>, cudaFuncAttributeMaxDynamicSharedMemorySize, SM_PV);
    cudaFuncSetAttribute(mma_gemm<0,2,0,2>, cudaFuncAttributeMaxDynamicSharedMemorySize, SM_PRJ);

    const size_t sCN = (size_t)CH * NPIX;
    const size_t sNN = (size_t)NPIX * NPIX;

    // 0. prep weights/biases
    prep_kernel<<<(4*CH*CH + 3*CH + 255)/256, 256>>>(wq, wk, wv, wp, bq, bk, bv);

    // 1. GroupNorm (two-phase) -> bf16 h
    gn_stats<<<BATCH*CH, 256>>>(x);
    gn_apply<<<BATCH*CH, 256>>>(x, gamma, beta);

    // 2. fused qkv: A = stacked W plain, B = h trans (cp.async)
    dim3 gqkv(NPIX/128, (3*CH)/128, BATCH);
    mma_gemm<0,1,2,2><<<gqkv, 256, SM_QKV>>>(
        p_wb, p_hb, p_bias, nullptr, p_qb, p_kb, p_vb,
        nullptr, 1.0f, CH, CH, NPIX, NPIX, 0, sCN, sCN);

    // 3. exp-scores = exp(q^T k) + row partial sums
    dim3 gsc(NPIX/128, NPIX/128, BATCH);
    mma_gemm<1,1,4,2><<<gsc, 256, SM_SCO>>>(
        p_qb, p_kb, nullptr, nullptr, p_sb, nullptr, nullptr,
        nullptr, 1.0f, CH, NPIX, NPIX, NPIX, sCN, sCN, sNN);

    // 4. row sums -> 1/sum
    rowsum_kernel<<<BATCH*NPIX/256, 256>>>();

    // 5. PV split-K=2 on unnormalized exp-scores: bf16 partials
    dim3 gpv(NPIX/128, CH/128, BATCH*2);
    mma_gemm<0,0,3,2><<<gpv, 256, SM_PV>>>(
        p_vb, p_sb, nullptr, nullptr, p_pvb, nullptr, nullptr,
        nullptr, 1.0f, KSPLIT, NPIX, NPIX, NPIX, sCN, sNN, sCN);

    // 6. proj: A = Wp plain, B = bf16((pv0+pv1)*rinv) in-loader; fp32 out + bias + residual
    dim3 gprj(NPIX/128, CH/128, BATCH);
    mma_gemm<0,2,0,2><<<gprj, 256, SM_PRJ>>>(
        p_wpb, nullptr, bp, out, nullptr, nullptr, nullptr,
        x, 1.0f, CH, CH, NPIX, NPIX, 0, sCN, sCN);
}